// round 3
// baseline (speedup 1.0000x reference)
#include <cuda_runtime.h>
#include <cuda_bf16.h>
#include <string.h>

#define H       128
#define NBR     10
#define AF      35
#define BF      40            // ATOM_FDIM + BOND_FDIM
#define N_ATOMS 100000
#define N_BONDS 220000
#define N_MESS  20000
#define N_MOLS  2000
#define MSG_ROWS (N_MESS + N_BONDS)
#define KA      164           // 128 (nei) + 35 (fatoms) + 1 pad
#define TM      64            // rows per block tile
#define TB      256           // threads per block
#define WS      130           // Wsm transposed row stride (bond), floats
#define WSA     170           // Wsm transposed row stride (atom), floats

typedef unsigned long long ull;

// packed f32x2 FMA: d = a*b + d (elementwise on 2 floats)
#define FMA2(d, a, b) \
    asm("fma.rn.f32x2 %0, %1, %2, %0;" : "+l"(d) : "l"(a), "l"(b))

__device__ __forceinline__ float pairsum(ull v) {
    float lo = __int_as_float((int)(unsigned)(v & 0xffffffffull));
    float hi = __int_as_float((int)(unsigned)(v >> 32));
    return lo + hi;
}

// ---- scratch (device globals: allocation-free kernel_launch) ----
__device__ float g_msgA[(size_t)MSG_ROWS * H];
__device__ float g_msgB[(size_t)MSG_ROWS * H];
__device__ float g_binput[(size_t)N_BONDS * H];
__device__ float g_atomh[(size_t)N_ATOMS * H];

// ---------------------------------------------------------------
// copy tree_message into the head of both message ping-pong bufs
__global__ void tree_copy_kernel(const float* __restrict__ tree) {
    int i = blockIdx.x * blockDim.x + threadIdx.x;
    int n4 = N_MESS * H / 4;
    if (i < n4) {
        float4 v = ((const float4*)tree)[i];
        ((float4*)g_msgA)[i] = v;
        ((float4*)g_msgB)[i] = v;
    }
}

// ---------------------------------------------------------------
// binput = fbonds @ W_i ; msgA graph part = relu(binput)
__global__ void binput_kernel(const float* __restrict__ fbonds,
                              const float* __restrict__ W_i) {
    extern __shared__ float sm[];
    float* Asm = sm;             // [TM][BF]
    float* Wsm = sm + TM * BF;   // [BF][H]
    int m0 = blockIdx.x * TM;
    int tid = threadIdx.x;
    int warp = tid >> 5, lane = tid & 31;

    for (int i = tid * 4; i < BF * H; i += TB * 4)
        *(float4*)&Wsm[i] = *(const float4*)&W_i[i];
    for (int i = tid; i < TM * BF; i += TB) {
        int r = i / BF, c = i % BF;
        int m = m0 + r;
        Asm[i] = (m < N_BONDS) ? fbonds[(size_t)m * BF + c] : 0.f;
    }
    __syncthreads();

    float acc[8][4];
#pragma unroll
    for (int i = 0; i < 8; i++)
#pragma unroll
        for (int j = 0; j < 4; j++) acc[i][j] = 0.f;
    int n0 = lane * 4;
#pragma unroll
    for (int kk = 0; kk < BF; kk += 4) {
        float4 b0 = *(float4*)&Wsm[(kk + 0) * H + n0];
        float4 b1 = *(float4*)&Wsm[(kk + 1) * H + n0];
        float4 b2 = *(float4*)&Wsm[(kk + 2) * H + n0];
        float4 b3 = *(float4*)&Wsm[(kk + 3) * H + n0];
#pragma unroll
        for (int i = 0; i < 8; i++) {
            float4 a = *(float4*)&Asm[(warp * 8 + i) * BF + kk];
            acc[i][0] += a.x * b0.x + a.y * b1.x + a.z * b2.x + a.w * b3.x;
            acc[i][1] += a.x * b0.y + a.y * b1.y + a.z * b2.y + a.w * b3.y;
            acc[i][2] += a.x * b0.z + a.y * b1.z + a.z * b2.z + a.w * b3.z;
            acc[i][3] += a.x * b0.w + a.y * b1.w + a.z * b2.w + a.w * b3.w;
        }
    }
    float* graphA = g_msgA + (size_t)N_MESS * H;
#pragma unroll
    for (int i = 0; i < 8; i++) {
        int m = m0 + warp * 8 + i;
        if (m < N_BONDS) {
            float4 v = make_float4(acc[i][0], acc[i][1], acc[i][2], acc[i][3]);
            *(float4*)&g_binput[(size_t)m * H + n0] = v;
            float4 r = make_float4(fmaxf(v.x, 0.f), fmaxf(v.y, 0.f),
                                   fmaxf(v.z, 0.f), fmaxf(v.w, 0.f));
            *(float4*)&graphA[(size_t)m * H + n0] = r;
        }
    }
}

// ---------------------------------------------------------------
// one depth iter: dst_graph = relu(binput + gathersum(src_msg)@W_h)
// K-packed FFMA2 GEMM: acc pairs hold (even-k, odd-k) partial sums.
__global__ void __launch_bounds__(TB, 2)
bond_update_kernel(const float* __restrict__ src_msg,
                   float* __restrict__ dst_graph,
                   const int* __restrict__ bgraph,
                   const float* __restrict__ W_h) {
    extern __shared__ float sm[];
    float* Asm = sm;            // [TM][H] row-major
    float* Wsm = sm + TM * H;   // [H out][WS] transposed, k contiguous
    int m0 = blockIdx.x * TM;
    int tid = threadIdx.x;
    int warp = tid >> 5, lane = tid & 31;

    // W_h is [k][n]; store transposed Wsm[n][k]
    for (int i = tid; i < H * H; i += TB) {
        int k = i >> 7, n = i & (H - 1);
        Wsm[n * WS + k] = W_h[i];
    }

    // gather: warp handles 8 rows, lane handles cols [4*lane, 4*lane+4)
#pragma unroll
    for (int rr = 0; rr < 8; rr++) {
        int r = warp * 8 + rr;
        int m = m0 + r;
        float4 acc = make_float4(0.f, 0.f, 0.f, 0.f);
        if (m < N_BONDS) {
            const int* bg = &bgraph[m * NBR];
#pragma unroll
            for (int nb = 0; nb < NBR; nb++) {
                int idx = bg[nb];
                float4 v = *(const float4*)&src_msg[(size_t)idx * H + lane * 4];
                acc.x += v.x; acc.y += v.y; acc.z += v.z; acc.w += v.w;
            }
        }
        *(float4*)&Asm[r * H + lane * 4] = acc;
    }
    __syncthreads();

    // GEMM: thread -> 8 rows x 4 cols (cols lane, lane+32, lane+64, lane+96)
    ull acc[8][4];
#pragma unroll
    for (int i = 0; i < 8; i++)
#pragma unroll
        for (int j = 0; j < 4; j++) acc[i][j] = 0ull;

    const float* Arow = &Asm[warp * 8 * H];
#pragma unroll 2
    for (int kp = 0; kp < H / 2; kp++) {
        ull b0 = *(const ull*)&Wsm[(lane      ) * WS + 2 * kp];
        ull b1 = *(const ull*)&Wsm[(lane + 32 ) * WS + 2 * kp];
        ull b2 = *(const ull*)&Wsm[(lane + 64 ) * WS + 2 * kp];
        ull b3 = *(const ull*)&Wsm[(lane + 96 ) * WS + 2 * kp];
#pragma unroll
        for (int i = 0; i < 8; i++) {
            ull a = *(const ull*)&Arow[i * H + 2 * kp];
            FMA2(acc[i][0], a, b0);
            FMA2(acc[i][1], a, b1);
            FMA2(acc[i][2], a, b2);
            FMA2(acc[i][3], a, b3);
        }
    }

#pragma unroll
    for (int i = 0; i < 8; i++) {
        int m = m0 + warp * 8 + i;
        if (m < N_BONDS) {
#pragma unroll
            for (int j = 0; j < 4; j++) {
                int c = lane + 32 * j;
                float s = pairsum(acc[i][j]);
                float v = fmaxf(g_binput[(size_t)m * H + c] + s, 0.f);
                dst_graph[(size_t)m * H + c] = v;
            }
        }
    }
}

// ---------------------------------------------------------------
// atom_hiddens = relu([gathersum(msg), fatoms] @ Wreord + b_o)
// A cols [0,128)=nei, [128,163)=fatoms, 163=pad; W rows reordered to match.
__global__ void __launch_bounds__(TB, 1)
atom_kernel(const float* __restrict__ src_msg,
            const int* __restrict__ agraph,
            const float* __restrict__ fatoms,
            const float* __restrict__ W_o,
            const float* __restrict__ b_o) {
    extern __shared__ float sm[];
    float* Asm = sm;             // [TM][KA] row-major (stride 164)
    float* Wsm = sm + TM * KA;   // [H out][WSA] transposed, k contiguous
    int m0 = blockIdx.x * TM;
    int tid = threadIdx.x;
    int warp = tid >> 5, lane = tid & 31;

    for (int i = tid; i < H * KA; i += TB) {
        int k = i >> 7, n = i & (H - 1);
        float v;
        if (k < 128)      v = W_o[(size_t)(35 + k) * H + n];
        else if (k < 163) v = W_o[(size_t)(k - 128) * H + n];
        else              v = 0.f;
        Wsm[n * WSA + k] = v;
    }

    // nei gather into A[:, 0:128)
#pragma unroll
    for (int rr = 0; rr < 8; rr++) {
        int r = warp * 8 + rr;
        int m = m0 + r;
        float4 acc = make_float4(0.f, 0.f, 0.f, 0.f);
        if (m < N_ATOMS) {
            const int* ag = &agraph[m * NBR];
#pragma unroll
            for (int nb = 0; nb < NBR; nb++) {
                int idx = ag[nb];
                float4 v = *(const float4*)&src_msg[(size_t)idx * H + lane * 4];
                acc.x += v.x; acc.y += v.y; acc.z += v.z; acc.w += v.w;
            }
        }
        *(float4*)&Asm[r * KA + lane * 4] = acc;
    }
    // fatoms into A[:, 128:163), pad col 163
    for (int i = tid; i < TM * AF; i += TB) {
        int r = i / AF, c = i % AF;
        int m = m0 + r;
        Asm[r * KA + 128 + c] = (m < N_ATOMS) ? fatoms[(size_t)m * AF + c] : 0.f;
    }
    if (tid < TM) Asm[tid * KA + 163] = 0.f;
    __syncthreads();

    ull acc[8][4];
#pragma unroll
    for (int i = 0; i < 8; i++)
#pragma unroll
        for (int j = 0; j < 4; j++) acc[i][j] = 0ull;

    const float* Arow = &Asm[warp * 8 * KA];
#pragma unroll 2
    for (int kp = 0; kp < KA / 2; kp++) {
        ull b0 = *(const ull*)&Wsm[(lane      ) * WSA + 2 * kp];
        ull b1 = *(const ull*)&Wsm[(lane + 32 ) * WSA + 2 * kp];
        ull b2 = *(const ull*)&Wsm[(lane + 64 ) * WSA + 2 * kp];
        ull b3 = *(const ull*)&Wsm[(lane + 96 ) * WSA + 2 * kp];
#pragma unroll
        for (int i = 0; i < 8; i++) {
            ull a = *(const ull*)&Arow[i * KA + 2 * kp];
            FMA2(acc[i][0], a, b0);
            FMA2(acc[i][1], a, b1);
            FMA2(acc[i][2], a, b2);
            FMA2(acc[i][3], a, b3);
        }
    }

#pragma unroll
    for (int i = 0; i < 8; i++) {
        int m = m0 + warp * 8 + i;
        if (m < N_ATOMS) {
#pragma unroll
            for (int j = 0; j < 4; j++) {
                int c = lane + 32 * j;
                float s = pairsum(acc[i][j]);
                float v = fmaxf(s + b_o[c], 0.f);
                g_atomh[(size_t)m * H + c] = v;
            }
        }
    }
}

// ---------------------------------------------------------------
// per-molecule mean pool (mol_ids sorted -> contiguous ranges)
__device__ __forceinline__ int lowerb(const int* __restrict__ a, int n, int key) {
    int lo = 0, hi = n;
    while (lo < hi) {
        int mid = (lo + hi) >> 1;
        if (a[mid] < key) lo = mid + 1; else hi = mid;
    }
    return lo;
}

__global__ void pool_kernel(const int* __restrict__ mol_ids,
                            float* __restrict__ out) {
    int mol = blockIdx.x;
    int tid = threadIdx.x;
    int lo = lowerb(mol_ids, N_ATOMS, mol);
    int hi = lowerb(mol_ids, N_ATOMS, mol + 1);
    float s = 0.f;
    for (int a = lo; a < hi; a++)
        s += g_atomh[(size_t)a * H + tid];
    int cnt = hi - lo;
    out[(size_t)mol * H + tid] = cnt ? s / (float)cnt : 0.f;
}

// ---------------------------------------------------------------
extern "C" void kernel_launch(void* const* d_in, const int* in_sizes, int n_in,
                              void* d_out, int out_size) {
    const float *fatoms = nullptr, *fbonds = nullptr, *tree = nullptr;
    const float *W_i = nullptr, *W_h = nullptr, *W_o = nullptr, *b_o = nullptr;
    const int *agraph = nullptr, *bgraph = nullptr, *mol_ids = nullptr;
    for (int i = 0; i < n_in; i++) {
        switch (in_sizes[i]) {
            case 3500000: fatoms  = (const float*)d_in[i]; break;   // 100000*35
            case 8800000: fbonds  = (const float*)d_in[i]; break;   // 220000*40
            case 2560000: tree    = (const float*)d_in[i]; break;   // 20000*128
            case 1000000: agraph  = (const int*)d_in[i];   break;   // 100000*10
            case 2200000: bgraph  = (const int*)d_in[i];   break;   // 220000*10
            case 100000:  mol_ids = (const int*)d_in[i];   break;
            case 5120:    W_i     = (const float*)d_in[i]; break;   // 40*128
            case 16384:   W_h     = (const float*)d_in[i]; break;   // 128*128
            case 20864:   W_o     = (const float*)d_in[i]; break;   // 163*128
            case 128:     b_o     = (const float*)d_in[i]; break;
        }
    }

    const int BIN_SMEM  = (TM * BF + BF * H) * 4;       // ~30.75 KB
    const int BOND_SMEM = (TM * H + H * WS) * 4;        // 99,328 B
    const int ATOM_SMEM = (TM * KA + H * WSA) * 4;      // 129,024 B
    cudaFuncSetAttribute(bond_update_kernel,
                         cudaFuncAttributeMaxDynamicSharedMemorySize, BOND_SMEM);
    cudaFuncSetAttribute(atom_kernel,
                         cudaFuncAttributeMaxDynamicSharedMemorySize, ATOM_SMEM);

    float *msgA, *msgB;
    cudaGetSymbolAddress((void**)&msgA, g_msgA);
    cudaGetSymbolAddress((void**)&msgB, g_msgB);

    int tc_blocks = (N_MESS * H / 4 + 255) / 256;
    tree_copy_kernel<<<tc_blocks, 256>>>(tree);

    int grid_b = (N_BONDS + TM - 1) / TM;
    binput_kernel<<<grid_b, TB, BIN_SMEM>>>(fbonds, W_i);

    float* src = msgA;
    float* dst = msgB;
    for (int it = 0; it < 5; it++) {   // DEPTH-1
        bond_update_kernel<<<grid_b, TB, BOND_SMEM>>>(
            src, dst + (size_t)N_MESS * H, bgraph, W_h);
        float* t = src; src = dst; dst = t;
    }
    // final message lives in `src`

    int grid_a = (N_ATOMS + TM - 1) / TM;
    atom_kernel<<<grid_a, TB, ATOM_SMEM>>>(src, agraph, fatoms, W_o, b_o);

    pool_kernel<<<N_MOLS, H>>>(mol_ids, (float*)d_out);
}

// round 5
// speedup vs baseline: 1.4850x; 1.4850x over previous
#include <cuda_runtime.h>
#include <cuda_bf16.h>
#include <cstdint>

#define H       128
#define NBR     10
#define AF      35
#define BF      40            // ATOM_FDIM + BOND_FDIM
#define N_ATOMS 100000
#define N_BONDS 220000
#define N_MESS  20000
#define N_MOLS  2000
#define MSG_ROWS (N_MESS + N_BONDS)
#define KA      164           // 128 (nei) + 35 (fatoms) + 1 pad
#define TM      64            // rows per block tile (SIMT kernels)
#define TB      256           // threads per block (SIMT kernels)

// MMA bond kernel tiling
#define MT      256           // rows per block
#define MWARPS  16            // warps per block
#define ASTRIDE 136           // padded A row stride in bf16 (conflict-free frags)

// ---- scratch (device globals: allocation-free kernel_launch) ----
__device__ float g_msgA[(size_t)MSG_ROWS * H];
__device__ float g_msgB[(size_t)MSG_ROWS * H];
__device__ float g_binput[(size_t)N_BONDS * H];
__device__ float g_atomh[(size_t)N_ATOMS * H];
// W_h packed in mma.sync B-fragment order: [kstep 8][ntile 16][lane 32] uint2
__device__ uint2 g_wf_hi[8 * 16 * 32];
__device__ uint2 g_wf_lo[8 * 16 * 32];

// mma.sync m16n8k16 bf16 (f32 accum) — compute_80 feature, legal on sm_103 base
#define MMA16816(c, a0, a1, a2, a3, b0, b1) \
    asm volatile("mma.sync.aligned.m16n8k16.row.col.f32.bf16.bf16.f32 " \
        "{%0,%1,%2,%3}, {%4,%5,%6,%7}, {%8,%9}, {%0,%1,%2,%3};" \
        : "+f"((c)[0]), "+f"((c)[1]), "+f"((c)[2]), "+f"((c)[3]) \
        : "r"(a0), "r"(a1), "r"(a2), "r"(a3), "r"(b0), "r"(b1))

__device__ __forceinline__ unsigned short bf16hi(float v) {
    return __bfloat16_as_ushort(__float2bfloat16_rn(v));
}

// ---------------------------------------------------------------
// copy tree_message into the head of both message ping-pong bufs
__global__ void tree_copy_kernel(const float* __restrict__ tree) {
    int i = blockIdx.x * blockDim.x + threadIdx.x;
    int n4 = N_MESS * H / 4;
    if (i < n4) {
        float4 v = ((const float4*)tree)[i];
        ((float4*)g_msgA)[i] = v;
        ((float4*)g_msgB)[i] = v;
    }
}

// ---------------------------------------------------------------
// W_h [k][n] fp32 -> bf16 hi/lo B-fragments for mma.sync m16n8k16
// entry i = s*512 + t*32 + lane;  g=lane>>2, tig=lane&3; n=t*8+g; k0=s*16+tig*2
// b0 = {B[k0][n], B[k0+1][n]}, b1 = {B[k0+8][n], B[k0+9][n]}
__global__ void prep_w_kernel(const float* __restrict__ W_h) {
    int i = blockIdx.x * blockDim.x + threadIdx.x;
    if (i >= 8 * 16 * 32) return;
    int lane = i & 31, t = (i >> 5) & 15, s = i >> 9;
    int g = lane >> 2, tig = lane & 3;
    int n = t * 8 + g;
    int k0 = s * 16 + tig * 2;
    float w00 = W_h[(k0 + 0) * H + n];
    float w01 = W_h[(k0 + 1) * H + n];
    float w10 = W_h[(k0 + 8) * H + n];
    float w11 = W_h[(k0 + 9) * H + n];
    unsigned short h00 = bf16hi(w00), h01 = bf16hi(w01);
    unsigned short h10 = bf16hi(w10), h11 = bf16hi(w11);
    float r00 = w00 - __bfloat162float(__ushort_as_bfloat16(h00));
    float r01 = w01 - __bfloat162float(__ushort_as_bfloat16(h01));
    float r10 = w10 - __bfloat162float(__ushort_as_bfloat16(h10));
    float r11 = w11 - __bfloat162float(__ushort_as_bfloat16(h11));
    g_wf_hi[i] = make_uint2((uint32_t)h00 | ((uint32_t)h01 << 16),
                            (uint32_t)h10 | ((uint32_t)h11 << 16));
    g_wf_lo[i] = make_uint2((uint32_t)bf16hi(r00) | ((uint32_t)bf16hi(r01) << 16),
                            (uint32_t)bf16hi(r10) | ((uint32_t)bf16hi(r11) << 16));
}

// ---------------------------------------------------------------
// binput = fbonds @ W_i ; msgA graph part = relu(binput)   (SIMT)
__global__ void binput_kernel(const float* __restrict__ fbonds,
                              const float* __restrict__ W_i) {
    extern __shared__ float sm[];
    float* Asm = sm;             // [TM][BF]
    float* Wsm = sm + TM * BF;   // [BF][H]
    int m0 = blockIdx.x * TM;
    int tid = threadIdx.x;
    int warp = tid >> 5, lane = tid & 31;

    for (int i = tid * 4; i < BF * H; i += TB * 4)
        *(float4*)&Wsm[i] = *(const float4*)&W_i[i];
    for (int i = tid; i < TM * BF; i += TB) {
        int r = i / BF, c = i % BF;
        int m = m0 + r;
        Asm[i] = (m < N_BONDS) ? fbonds[(size_t)m * BF + c] : 0.f;
    }
    __syncthreads();

    float acc[8][4];
#pragma unroll
    for (int i = 0; i < 8; i++)
#pragma unroll
        for (int j = 0; j < 4; j++) acc[i][j] = 0.f;
    int n0 = lane * 4;
#pragma unroll
    for (int kk = 0; kk < BF; kk += 4) {
        float4 b0 = *(float4*)&Wsm[(kk + 0) * H + n0];
        float4 b1 = *(float4*)&Wsm[(kk + 1) * H + n0];
        float4 b2 = *(float4*)&Wsm[(kk + 2) * H + n0];
        float4 b3 = *(float4*)&Wsm[(kk + 3) * H + n0];
#pragma unroll
        for (int i = 0; i < 8; i++) {
            float4 a = *(float4*)&Asm[(warp * 8 + i) * BF + kk];
            acc[i][0] += a.x * b0.x + a.y * b1.x + a.z * b2.x + a.w * b3.x;
            acc[i][1] += a.x * b0.y + a.y * b1.y + a.z * b2.y + a.w * b3.y;
            acc[i][2] += a.x * b0.z + a.y * b1.z + a.z * b2.z + a.w * b3.z;
            acc[i][3] += a.x * b0.w + a.y * b1.w + a.z * b2.w + a.w * b3.w;
        }
    }
    float* graphA = g_msgA + (size_t)N_MESS * H;
#pragma unroll
    for (int i = 0; i < 8; i++) {
        int m = m0 + warp * 8 + i;
        if (m < N_BONDS) {
            float4 v = make_float4(acc[i][0], acc[i][1], acc[i][2], acc[i][3]);
            *(float4*)&g_binput[(size_t)m * H + n0] = v;
            float4 r = make_float4(fmaxf(v.x, 0.f), fmaxf(v.y, 0.f),
                                   fmaxf(v.z, 0.f), fmaxf(v.w, 0.f));
            *(float4*)&graphA[(size_t)m * H + n0] = r;
        }
    }
}

// ---------------------------------------------------------------
// one depth iter via mma.sync: dst = relu(binput + gathersum(src)@W_h)
// A,W in bf16 hi/lo; D = Ah*Bh + Ah*Bl + Al*Bh (fp32 accum on tensor pipe)
__global__ void __launch_bounds__(512, 1)
bond_mma_kernel(const float* __restrict__ src_msg,
                float* __restrict__ dst_graph,
                const int* __restrict__ bgraph) {
    extern __shared__ char smem[];
    __nv_bfloat16* Ahi = (__nv_bfloat16*)smem;          // [MT][ASTRIDE]
    __nv_bfloat16* Alo = Ahi + MT * ASTRIDE;
    uint2* WH = (uint2*)(Alo + MT * ASTRIDE);           // [4096]
    uint2* WL = WH + 4096;

    int tid = threadIdx.x, warp = tid >> 5, lane = tid & 31;
    int m0 = blockIdx.x * MT;

    // stage W fragments (64 KB) into smem
    for (int i = tid; i < 4096; i += 512) {
        WH[i] = g_wf_hi[i];
        WL[i] = g_wf_lo[i];
    }

    // gather + bf16 hi/lo split: warp -> 16 rows, lane -> cols [4l,4l+4)
    for (int i = 0; i < 16; i++) {
        int r = warp * 16 + i;
        int m = m0 + r;
        float4 acc = make_float4(0.f, 0.f, 0.f, 0.f);
        if (m < N_BONDS) {
            const int* bg = &bgraph[m * NBR];
#pragma unroll
            for (int nb = 0; nb < NBR; nb++) {
                int idx = __ldg(&bg[nb]);
                float4 v = *(const float4*)&src_msg[(size_t)idx * H + lane * 4];
                acc.x += v.x; acc.y += v.y; acc.z += v.z; acc.w += v.w;
            }
        }
        float a[4] = {acc.x, acc.y, acc.z, acc.w};
        unsigned short hs[4], ls[4];
#pragma unroll
        for (int j = 0; j < 4; j++) {
            hs[j] = bf16hi(a[j]);
            float rr = a[j] - __bfloat162float(__ushort_as_bfloat16(hs[j]));
            ls[j] = bf16hi(rr);
        }
        *(uint2*)&Ahi[r * ASTRIDE + lane * 4] =
            make_uint2((uint32_t)hs[0] | ((uint32_t)hs[1] << 16),
                       (uint32_t)hs[2] | ((uint32_t)hs[3] << 16));
        *(uint2*)&Alo[r * ASTRIDE + lane * 4] =
            make_uint2((uint32_t)ls[0] | ((uint32_t)ls[1] << 16),
                       (uint32_t)ls[2] | ((uint32_t)ls[3] << 16));
    }
    __syncthreads();

    // MMA: each warp computes rows [warp*16, warp*16+16) x all 128 cols
    int g = lane >> 2, tig = lane & 3;
    int r0 = warp * 16 + g;          // rows r0 and r0+8
    float c[16][4];
#pragma unroll
    for (int t = 0; t < 16; t++)
#pragma unroll
        for (int j = 0; j < 4; j++) c[t][j] = 0.f;

#pragma unroll
    for (int s = 0; s < 8; s++) {
        int k0 = s * 16 + tig * 2;
        uint32_t ah0 = *(const uint32_t*)&Ahi[(r0    ) * ASTRIDE + k0];
        uint32_t ah1 = *(const uint32_t*)&Ahi[(r0 + 8) * ASTRIDE + k0];
        uint32_t ah2 = *(const uint32_t*)&Ahi[(r0    ) * ASTRIDE + k0 + 8];
        uint32_t ah3 = *(const uint32_t*)&Ahi[(r0 + 8) * ASTRIDE + k0 + 8];
        uint32_t al0 = *(const uint32_t*)&Alo[(r0    ) * ASTRIDE + k0];
        uint32_t al1 = *(const uint32_t*)&Alo[(r0 + 8) * ASTRIDE + k0];
        uint32_t al2 = *(const uint32_t*)&Alo[(r0    ) * ASTRIDE + k0 + 8];
        uint32_t al3 = *(const uint32_t*)&Alo[(r0 + 8) * ASTRIDE + k0 + 8];
#pragma unroll
        for (int t = 0; t < 16; t++) {
            uint2 bh = WH[s * 512 + t * 32 + lane];
            uint2 bl = WL[s * 512 + t * 32 + lane];
            MMA16816(c[t], ah0, ah1, ah2, ah3, bh.x, bh.y);
            MMA16816(c[t], ah0, ah1, ah2, ah3, bl.x, bl.y);
            MMA16816(c[t], al0, al1, al2, al3, bh.x, bh.y);
        }
    }

    // epilogue: +binput, relu, store fp32
    int mA = m0 + r0;
    int mB = mA + 8;
#pragma unroll
    for (int t = 0; t < 16; t++) {
        int n0 = t * 8 + tig * 2;
        if (mA < N_BONDS) {
            float2 bi = *(const float2*)&g_binput[(size_t)mA * H + n0];
            float2 o = make_float2(fmaxf(bi.x + c[t][0], 0.f),
                                   fmaxf(bi.y + c[t][1], 0.f));
            *(float2*)&dst_graph[(size_t)mA * H + n0] = o;
        }
        if (mB < N_BONDS) {
            float2 bi = *(const float2*)&g_binput[(size_t)mB * H + n0];
            float2 o = make_float2(fmaxf(bi.x + c[t][2], 0.f),
                                   fmaxf(bi.y + c[t][3], 0.f));
            *(float2*)&dst_graph[(size_t)mB * H + n0] = o;
        }
    }
}

// ---------------------------------------------------------------
// atom_hiddens = relu([gathersum(msg), fatoms] @ Wreord + b_o)  (SIMT)
__global__ void atom_kernel(const float* __restrict__ src_msg,
                            const int* __restrict__ agraph,
                            const float* __restrict__ fatoms,
                            const float* __restrict__ W_o,
                            const float* __restrict__ b_o) {
    extern __shared__ float sm[];
    float* Asm = sm;             // [TM][KA]
    float* Wsm = sm + TM * KA;   // [KA][H]
    int m0 = blockIdx.x * TM;
    int tid = threadIdx.x;
    int warp = tid >> 5, lane = tid & 31;

    for (int i = tid * 4; i < KA * H; i += TB * 4) {
        int k = i >> 7;
        int n = i & (H - 1);
        float4 v;
        if (k < 128)       v = *(const float4*)&W_o[(size_t)(35 + k) * H + n];
        else if (k < 163)  v = *(const float4*)&W_o[(size_t)(k - 128) * H + n];
        else               v = make_float4(0.f, 0.f, 0.f, 0.f);
        *(float4*)&Wsm[i] = v;
    }

#pragma unroll
    for (int rr = 0; rr < 8; rr++) {
        int r = warp * 8 + rr;
        int m = m0 + r;
        float4 acc = make_float4(0.f, 0.f, 0.f, 0.f);
        if (m < N_ATOMS) {
            const int* ag = &agraph[m * NBR];
#pragma unroll
            for (int nb = 0; nb < NBR; nb++) {
                int idx = ag[nb];
                float4 v = *(const float4*)&src_msg[(size_t)idx * H + lane * 4];
                acc.x += v.x; acc.y += v.y; acc.z += v.z; acc.w += v.w;
            }
        }
        *(float4*)&Asm[r * KA + lane * 4] = acc;
    }
    for (int i = tid; i < TM * AF; i += TB) {
        int r = i / AF, c = i % AF;
        int m = m0 + r;
        Asm[r * KA + 128 + c] = (m < N_ATOMS) ? fatoms[(size_t)m * AF + c] : 0.f;
    }
    if (tid < TM) Asm[tid * KA + 163] = 0.f;
    __syncthreads();

    float acc[8][4];
#pragma unroll
    for (int i = 0; i < 8; i++)
#pragma unroll
        for (int j = 0; j < 4; j++) acc[i][j] = 0.f;
    int n0 = lane * 4;
    for (int kk = 0; kk < KA; kk += 4) {
        float4 b0 = *(float4*)&Wsm[(kk + 0) * H + n0];
        float4 b1 = *(float4*)&Wsm[(kk + 1) * H + n0];
        float4 b2 = *(float4*)&Wsm[(kk + 2) * H + n0];
        float4 b3 = *(float4*)&Wsm[(kk + 3) * H + n0];
#pragma unroll
        for (int i = 0; i < 8; i++) {
            float4 a = *(float4*)&Asm[(warp * 8 + i) * KA + kk];
            acc[i][0] += a.x * b0.x + a.y * b1.x + a.z * b2.x + a.w * b3.x;
            acc[i][1] += a.x * b0.y + a.y * b1.y + a.z * b2.y + a.w * b3.y;
            acc[i][2] += a.x * b0.z + a.y * b1.z + a.z * b2.z + a.w * b3.z;
            acc[i][3] += a.x * b0.w + a.y * b1.w + a.z * b2.w + a.w * b3.w;
        }
    }
    float4 bo = *(const float4*)&b_o[n0];
#pragma unroll
    for (int i = 0; i < 8; i++) {
        int m = m0 + warp * 8 + i;
        if (m < N_ATOMS) {
            float4 o = make_float4(fmaxf(acc[i][0] + bo.x, 0.f),
                                   fmaxf(acc[i][1] + bo.y, 0.f),
                                   fmaxf(acc[i][2] + bo.z, 0.f),
                                   fmaxf(acc[i][3] + bo.w, 0.f));
            *(float4*)&g_atomh[(size_t)m * H + n0] = o;
        }
    }
}

// ---------------------------------------------------------------
__device__ __forceinline__ int lowerb(const int* __restrict__ a, int n, int key) {
    int lo = 0, hi = n;
    while (lo < hi) {
        int mid = (lo + hi) >> 1;
        if (a[mid] < key) lo = mid + 1; else hi = mid;
    }
    return lo;
}

__global__ void pool_kernel(const int* __restrict__ mol_ids,
                            float* __restrict__ out) {
    int mol = blockIdx.x;
    int tid = threadIdx.x;
    int lo = lowerb(mol_ids, N_ATOMS, mol);
    int hi = lowerb(mol_ids, N_ATOMS, mol + 1);
    float s = 0.f;
    for (int a = lo; a < hi; a++)
        s += g_atomh[(size_t)a * H + tid];
    int cnt = hi - lo;
    out[(size_t)mol * H + tid] = cnt ? s / (float)cnt : 0.f;
}

// ---------------------------------------------------------------
extern "C" void kernel_launch(void* const* d_in, const int* in_sizes, int n_in,
                              void* d_out, int out_size) {
    const float *fatoms = nullptr, *fbonds = nullptr, *tree = nullptr;
    const float *W_i = nullptr, *W_h = nullptr, *W_o = nullptr, *b_o = nullptr;
    const int *agraph = nullptr, *bgraph = nullptr, *mol_ids = nullptr;
    for (int i = 0; i < n_in; i++) {
        switch (in_sizes[i]) {
            case 3500000: fatoms  = (const float*)d_in[i]; break;   // 100000*35
            case 8800000: fbonds  = (const float*)d_in[i]; break;   // 220000*40
            case 2560000: tree    = (const float*)d_in[i]; break;   // 20000*128
            case 1000000: agraph  = (const int*)d_in[i];   break;   // 100000*10
            case 2200000: bgraph  = (const int*)d_in[i];   break;   // 220000*10
            case 100000:  mol_ids = (const int*)d_in[i];   break;
            case 5120:    W_i     = (const float*)d_in[i]; break;   // 40*128
            case 16384:   W_h     = (const float*)d_in[i]; break;   // 128*128
            case 20864:   W_o     = (const float*)d_in[i]; break;   // 163*128
            case 128:     b_o     = (const float*)d_in[i]; break;
        }
    }

    const int BIN_SMEM  = (TM * BF + BF * H) * 4;
    const int ATOM_SMEM = (TM * KA + KA * H) * 4;
    const int BOND_SMEM = MT * ASTRIDE * 2 * 2 + 4096 * 8 * 2;  // 139264 + 65536
    cudaFuncSetAttribute(bond_mma_kernel,
                         cudaFuncAttributeMaxDynamicSharedMemorySize, BOND_SMEM);
    cudaFuncSetAttribute(atom_kernel,
                         cudaFuncAttributeMaxDynamicSharedMemorySize, ATOM_SMEM);

    float *msgA, *msgB;
    cudaGetSymbolAddress((void**)&msgA, g_msgA);
    cudaGetSymbolAddress((void**)&msgB, g_msgB);

    int tc_blocks = (N_MESS * H / 4 + 255) / 256;
    tree_copy_kernel<<<tc_blocks, 256>>>(tree);
    prep_w_kernel<<<(8 * 16 * 32 + 255) / 256, 256>>>(W_h);

    int grid_b = (N_BONDS + TM - 1) / TM;
    binput_kernel<<<grid_b, TB, BIN_SMEM>>>(fbonds, W_i);

    float* src = msgA;
    float* dst = msgB;
    int grid_mma = (N_BONDS + MT - 1) / MT;   // 860
    for (int it = 0; it < 5; it++) {          // DEPTH-1
        bond_mma_kernel<<<grid_mma, 512, BOND_SMEM>>>(
            src, dst + (size_t)N_MESS * H, bgraph);
        float* t = src; src = dst; dst = t;
    }

    int grid_a = (N_ATOMS + TM - 1) / TM;
    atom_kernel<<<grid_a, TB, ATOM_SMEM>>>(src, agraph, fatoms, W_o, b_o);

    pool_kernel<<<N_MOLS, H>>>(mol_ids, (float*)d_out);
}

// round 7
// speedup vs baseline: 1.7288x; 1.1642x over previous
#include <cuda_runtime.h>
#include <cuda_bf16.h>
#include <cstdint>

#define H       128
#define NBR     10
#define AF      35
#define BF      40            // ATOM_FDIM + BOND_FDIM
#define N_ATOMS 100000
#define N_BONDS 220000
#define N_MESS  20000
#define N_MOLS  2000
#define MSG_ROWS (N_MESS + N_BONDS)
#define TM      64            // rows per block tile (SIMT binput)
#define TB      256

// bond mma kernel tiling
#define BMT     64            // rows per block
#define ASTR    136           // A row stride (bf16), conflict-free fragments
// atom mma kernel tiling
#define KA2     176           // padded K (11 k-steps of 16)
#define ASTRA   184           // A row stride (bf16), conflict-free fragments
#define NS_A    11            // k-steps for atom

// ---- scratch (device globals: allocation-free kernel_launch) ----
__device__ float g_msgA[(size_t)MSG_ROWS * H];
__device__ float g_msgB[(size_t)MSG_ROWS * H];
__device__ float g_binput[(size_t)N_BONDS * H];
__device__ float g_atomh[(size_t)N_ATOMS * H];
// W_h fragments: [kstep 8][ntile 16][lane 32] uint2, hi & lo planes
__device__ uint2 g_wf_hi[8 * 16 * 32];
__device__ uint2 g_wf_lo[8 * 16 * 32];
// W_o (reordered+padded) fragments: [kstep 11][ntile 16][lane 32]
__device__ uint2 g_wfo_hi[NS_A * 16 * 32];
__device__ uint2 g_wfo_lo[NS_A * 16 * 32];

#define MMA16816(c, a0, a1, a2, a3, b0, b1) \
    asm volatile("mma.sync.aligned.m16n8k16.row.col.f32.bf16.bf16.f32 " \
        "{%0,%1,%2,%3}, {%4,%5,%6,%7}, {%8,%9}, {%0,%1,%2,%3};" \
        : "+f"((c)[0]), "+f"((c)[1]), "+f"((c)[2]), "+f"((c)[3]) \
        : "r"(a0), "r"(a1), "r"(a2), "r"(a3), "r"(b0), "r"(b1))

__device__ __forceinline__ unsigned short bf16hi(float v) {
    return __bfloat16_as_ushort(__float2bfloat16_rn(v));
}
__device__ __forceinline__ void split2(float v, unsigned short& h, unsigned short& l) {
    h = bf16hi(v);
    l = bf16hi(v - __bfloat162float(__ushort_as_bfloat16(h)));
}

// ---------------------------------------------------------------
__global__ void tree_copy_kernel(const float* __restrict__ tree) {
    int i = blockIdx.x * blockDim.x + threadIdx.x;
    int n4 = N_MESS * H / 4;
    if (i < n4) {
        float4 v = ((const float4*)tree)[i];
        ((float4*)g_msgA)[i] = v;
        ((float4*)g_msgB)[i] = v;
    }
}

// ---------------------------------------------------------------
// W_h [k][n] -> bf16 hi/lo B-fragments (m16n8k16):
// i = s*512 + t*32 + lane; g=lane>>2, tig=lane&3; n=t*8+g; k0=s*16+tig*2
__global__ void prep_w_kernel(const float* __restrict__ W_h) {
    int i = blockIdx.x * blockDim.x + threadIdx.x;
    if (i >= 8 * 16 * 32) return;
    int lane = i & 31, t = (i >> 5) & 15, s = i >> 9;
    int g = lane >> 2, tig = lane & 3;
    int n = t * 8 + g;
    int k0 = s * 16 + tig * 2;
    float w[4] = { W_h[(k0 + 0) * H + n], W_h[(k0 + 1) * H + n],
                   W_h[(k0 + 8) * H + n], W_h[(k0 + 9) * H + n] };
    unsigned short h[4], l[4];
#pragma unroll
    for (int j = 0; j < 4; j++) split2(w[j], h[j], l[j]);
    g_wf_hi[i] = make_uint2((uint32_t)h[0] | ((uint32_t)h[1] << 16),
                            (uint32_t)h[2] | ((uint32_t)h[3] << 16));
    g_wf_lo[i] = make_uint2((uint32_t)l[0] | ((uint32_t)l[1] << 16),
                            (uint32_t)l[2] | ((uint32_t)l[3] << 16));
}

// W_o reordered (A col k: k<128 -> W_o row 35+k; 128..162 -> row k-128; else 0)
__device__ __forceinline__ float wo_val(const float* W_o, int k, int n) {
    if (k < 128)  return W_o[(size_t)(35 + k) * H + n];
    if (k < 163)  return W_o[(size_t)(k - 128) * H + n];
    return 0.f;
}
__global__ void prep_wo_kernel(const float* __restrict__ W_o) {
    int i = blockIdx.x * blockDim.x + threadIdx.x;
    if (i >= NS_A * 16 * 32) return;
    int lane = i & 31, t = (i >> 5) & 15, s = i >> 9;
    int g = lane >> 2, tig = lane & 3;
    int n = t * 8 + g;
    int k0 = s * 16 + tig * 2;
    float w[4] = { wo_val(W_o, k0 + 0, n), wo_val(W_o, k0 + 1, n),
                   wo_val(W_o, k0 + 8, n), wo_val(W_o, k0 + 9, n) };
    unsigned short h[4], l[4];
#pragma unroll
    for (int j = 0; j < 4; j++) split2(w[j], h[j], l[j]);
    g_wfo_hi[i] = make_uint2((uint32_t)h[0] | ((uint32_t)h[1] << 16),
                             (uint32_t)h[2] | ((uint32_t)h[3] << 16));
    g_wfo_lo[i] = make_uint2((uint32_t)l[0] | ((uint32_t)l[1] << 16),
                             (uint32_t)l[2] | ((uint32_t)l[3] << 16));
}

// ---------------------------------------------------------------
// binput = fbonds @ W_i ; msgA graph part = relu(binput)   (SIMT)
__global__ void binput_kernel(const float* __restrict__ fbonds,
                              const float* __restrict__ W_i) {
    extern __shared__ float sm[];
    float* Asm = sm;             // [TM][BF]
    float* Wsm = sm + TM * BF;   // [BF][H]
    int m0 = blockIdx.x * TM;
    int tid = threadIdx.x;
    int warp = tid >> 5, lane = tid & 31;

    for (int i = tid * 4; i < BF * H; i += TB * 4)
        *(float4*)&Wsm[i] = *(const float4*)&W_i[i];
    for (int i = tid; i < TM * BF; i += TB) {
        int r = i / BF, c = i % BF;
        int m = m0 + r;
        Asm[i] = (m < N_BONDS) ? fbonds[(size_t)m * BF + c] : 0.f;
    }
    __syncthreads();

    float acc[8][4];
#pragma unroll
    for (int i = 0; i < 8; i++)
#pragma unroll
        for (int j = 0; j < 4; j++) acc[i][j] = 0.f;
    int n0 = lane * 4;
#pragma unroll
    for (int kk = 0; kk < BF; kk += 4) {
        float4 b0 = *(float4*)&Wsm[(kk + 0) * H + n0];
        float4 b1 = *(float4*)&Wsm[(kk + 1) * H + n0];
        float4 b2 = *(float4*)&Wsm[(kk + 2) * H + n0];
        float4 b3 = *(float4*)&Wsm[(kk + 3) * H + n0];
#pragma unroll
        for (int i = 0; i < 8; i++) {
            float4 a = *(float4*)&Asm[(warp * 8 + i) * BF + kk];
            acc[i][0] += a.x * b0.x + a.y * b1.x + a.z * b2.x + a.w * b3.x;
            acc[i][1] += a.x * b0.y + a.y * b1.y + a.z * b2.y + a.w * b3.y;
            acc[i][2] += a.x * b0.z + a.y * b1.z + a.z * b2.z + a.w * b3.z;
            acc[i][3] += a.x * b0.w + a.y * b1.w + a.z * b2.w + a.w * b3.w;
        }
    }
    float* graphA = g_msgA + (size_t)N_MESS * H;
#pragma unroll
    for (int i = 0; i < 8; i++) {
        int m = m0 + warp * 8 + i;
        if (m < N_BONDS) {
            float4 v = make_float4(acc[i][0], acc[i][1], acc[i][2], acc[i][3]);
            *(float4*)&g_binput[(size_t)m * H + n0] = v;
            float4 r = make_float4(fmaxf(v.x, 0.f), fmaxf(v.y, 0.f),
                                   fmaxf(v.z, 0.f), fmaxf(v.w, 0.f));
            *(float4*)&graphA[(size_t)m * H + n0] = r;
        }
    }
}

// ---------------------------------------------------------------
// bond iter: dst = relu(binput + gathersum(src)@W_h)
// MT=64, 8 warps; warp tile = 16 rows x 64 cols; W hi+lo in smem.
// 2 CTAs/SM -> gather (LSU) of one CTA overlaps MMA (tensor) of the other.
__global__ void __launch_bounds__(256, 2)
bond_mma_kernel(const float* __restrict__ src_msg,
                float* __restrict__ dst_graph,
                const int* __restrict__ bgraph) {
    extern __shared__ char smem[];
    __nv_bfloat16* Ahi = (__nv_bfloat16*)smem;            // [BMT][ASTR]
    __nv_bfloat16* Alo = Ahi + BMT * ASTR;
    uint2* WH = (uint2*)(Alo + BMT * ASTR);               // [4096]
    uint2* WL = WH + 4096;

    int tid = threadIdx.x, warp = tid >> 5, lane = tid & 31;
    int m0 = blockIdx.x * BMT;

    // stage W fragments (64 KB = 2 x 2048 uint4)
    {
        const uint4* sh = (const uint4*)g_wf_hi;
        const uint4* sl = (const uint4*)g_wf_lo;
        uint4* dh = (uint4*)WH;
        uint4* dl = (uint4*)WL;
        for (int i = tid; i < 2048; i += 256) { dh[i] = sh[i]; dl[i] = sl[i]; }
    }

    // gather: warp -> 8 rows, lane -> cols [4l, 4l+4)
#pragma unroll
    for (int i = 0; i < 8; i++) {
        int r = warp * 8 + i;
        int m = m0 + r;
        float4 acc = make_float4(0.f, 0.f, 0.f, 0.f);
        if (m < N_BONDS) {
            const int* bg = &bgraph[m * NBR];
#pragma unroll
            for (int nb = 0; nb < NBR; nb++) {
                int idx = __ldg(&bg[nb]);
                float4 v = *(const float4*)&src_msg[(size_t)idx * H + lane * 4];
                acc.x += v.x; acc.y += v.y; acc.z += v.z; acc.w += v.w;
            }
        }
        float a[4] = {acc.x, acc.y, acc.z, acc.w};
        unsigned short hs[4], ls[4];
#pragma unroll
        for (int j = 0; j < 4; j++) split2(a[j], hs[j], ls[j]);
        *(uint2*)&Ahi[r * ASTR + lane * 4] =
            make_uint2((uint32_t)hs[0] | ((uint32_t)hs[1] << 16),
                       (uint32_t)hs[2] | ((uint32_t)hs[3] << 16));
        *(uint2*)&Alo[r * ASTR + lane * 4] =
            make_uint2((uint32_t)ls[0] | ((uint32_t)ls[1] << 16),
                       (uint32_t)ls[2] | ((uint32_t)ls[3] << 16));
    }
    __syncthreads();

    // MMA: warp (w&3) -> row half, (w>>2) -> col half
    int g = lane >> 2, tig = lane & 3;
    int r0 = (warp & 3) * 16 + g;
    int tbase = (warp >> 2) * 8;
    float c[8][4];
#pragma unroll
    for (int t = 0; t < 8; t++)
#pragma unroll
        for (int j = 0; j < 4; j++) c[t][j] = 0.f;

#pragma unroll
    for (int s = 0; s < 8; s++) {
        int k0 = s * 16 + tig * 2;
        uint32_t ah0 = *(const uint32_t*)&Ahi[(r0    ) * ASTR + k0];
        uint32_t ah1 = *(const uint32_t*)&Ahi[(r0 + 8) * ASTR + k0];
        uint32_t ah2 = *(const uint32_t*)&Ahi[(r0    ) * ASTR + k0 + 8];
        uint32_t ah3 = *(const uint32_t*)&Ahi[(r0 + 8) * ASTR + k0 + 8];
        uint32_t al0 = *(const uint32_t*)&Alo[(r0    ) * ASTR + k0];
        uint32_t al1 = *(const uint32_t*)&Alo[(r0 + 8) * ASTR + k0];
        uint32_t al2 = *(const uint32_t*)&Alo[(r0    ) * ASTR + k0 + 8];
        uint32_t al3 = *(const uint32_t*)&Alo[(r0 + 8) * ASTR + k0 + 8];
#pragma unroll
        for (int t = 0; t < 8; t++) {
            uint2 bh = WH[s * 512 + (tbase + t) * 32 + lane];
            uint2 bl = WL[s * 512 + (tbase + t) * 32 + lane];
            MMA16816(c[t], ah0, ah1, ah2, ah3, bh.x, bh.y);
            MMA16816(c[t], ah0, ah1, ah2, ah3, bl.x, bl.y);
            MMA16816(c[t], al0, al1, al2, al3, bh.x, bh.y);
        }
    }

    // epilogue
    int mA = m0 + r0;
    int mB = mA + 8;
    int ncol0 = (warp >> 2) * 64 + tig * 2;
#pragma unroll
    for (int t = 0; t < 8; t++) {
        int n0 = ncol0 + t * 8;
        if (mA < N_BONDS) {
            float2 bi = *(const float2*)&g_binput[(size_t)mA * H + n0];
            float2 o = make_float2(fmaxf(bi.x + c[t][0], 0.f),
                                   fmaxf(bi.y + c[t][1], 0.f));
            *(float2*)&dst_graph[(size_t)mA * H + n0] = o;
        }
        if (mB < N_BONDS) {
            float2 bi = *(const float2*)&g_binput[(size_t)mB * H + n0];
            float2 o = make_float2(fmaxf(bi.x + c[t][2], 0.f),
                                   fmaxf(bi.y + c[t][3], 0.f));
            *(float2*)&dst_graph[(size_t)mB * H + n0] = o;
        }
    }
}

// ---------------------------------------------------------------
// atom: g_atomh = relu([nei(128)|fatoms(35)|pad] @ Wo_frag + b_o)  via mma
// MT=64, 8 warps, warp tile 16x64; Wo hi in smem, Wo lo via __ldg (L2).
__global__ void __launch_bounds__(256, 2)
atom_mma_kernel(const float* __restrict__ src_msg,
                const int* __restrict__ agraph,
                const float* __restrict__ fatoms,
                const float* __restrict__ b_o) {
    extern __shared__ char smem[];
    __nv_bfloat16* Ahi = (__nv_bfloat16*)smem;            // [64][ASTRA]
    __nv_bfloat16* Alo = Ahi + 64 * ASTRA;
    uint2* WH = (uint2*)(Alo + 64 * ASTRA);               // [NS_A*512]

    int tid = threadIdx.x, warp = tid >> 5, lane = tid & 31;
    int m0 = blockIdx.x * 64;

    // stage Wo hi fragments: NS_A*512 uint2 = 45056 B = 2816 uint4
    {
        const uint4* sh = (const uint4*)g_wfo_hi;
        uint4* dh = (uint4*)WH;
        for (int i = tid; i < 2816; i += 256) dh[i] = sh[i];
    }

    // nei gather into cols [0,128)
#pragma unroll
    for (int i = 0; i < 8; i++) {
        int r = warp * 8 + i;
        int m = m0 + r;
        float4 acc = make_float4(0.f, 0.f, 0.f, 0.f);
        if (m < N_ATOMS) {
            const int* ag = &agraph[m * NBR];
#pragma unroll
            for (int nb = 0; nb < NBR; nb++) {
                int idx = __ldg(&ag[nb]);
                float4 v = *(const float4*)&src_msg[(size_t)idx * H + lane * 4];
                acc.x += v.x; acc.y += v.y; acc.z += v.z; acc.w += v.w;
            }
        }
        float a[4] = {acc.x, acc.y, acc.z, acc.w};
        unsigned short hs[4], ls[4];
#pragma unroll
        for (int j = 0; j < 4; j++) split2(a[j], hs[j], ls[j]);
        *(uint2*)&Ahi[r * ASTRA + lane * 4] =
            make_uint2((uint32_t)hs[0] | ((uint32_t)hs[1] << 16),
                       (uint32_t)hs[2] | ((uint32_t)hs[3] << 16));
        *(uint2*)&Alo[r * ASTRA + lane * 4] =
            make_uint2((uint32_t)ls[0] | ((uint32_t)ls[1] << 16),
                       (uint32_t)ls[2] | ((uint32_t)ls[3] << 16));
    }
    // fatoms into cols [128,163), zero pad [163,176)
    for (int i = tid; i < 64 * 48; i += 256) {
        int r = i / 48, cc = 128 + (i % 48);
        int m = m0 + r;
        float v = (cc < 163 && m < N_ATOMS)
                  ? fatoms[(size_t)m * AF + (cc - 128)] : 0.f;
        unsigned short h, l;
        split2(v, h, l);
        Ahi[r * ASTRA + cc] = __ushort_as_bfloat16(h);
        Alo[r * ASTRA + cc] = __ushort_as_bfloat16(l);
    }
    __syncthreads();

    int g = lane >> 2, tig = lane & 3;
    int r0 = (warp & 3) * 16 + g;
    int tbase = (warp >> 2) * 8;
    float c[8][4];
#pragma unroll
    for (int t = 0; t < 8; t++)
#pragma unroll
        for (int j = 0; j < 4; j++) c[t][j] = 0.f;

#pragma unroll
    for (int s = 0; s < NS_A; s++) {
        int k0 = s * 16 + tig * 2;
        uint32_t ah0 = *(const uint32_t*)&Ahi[(r0    ) * ASTRA + k0];
        uint32_t ah1 = *(const uint32_t*)&Ahi[(r0 + 8) * ASTRA + k0];
        uint32_t ah2 = *(const uint32_t*)&Ahi[(r0    ) * ASTRA + k0 + 8];
        uint32_t ah3 = *(const uint32_t*)&Ahi[(r0 + 8) * ASTRA + k0 + 8];
        uint32_t al0 = *(const uint32_t*)&Alo[(r0    ) * ASTRA + k0];
        uint32_t al1 = *(const uint32_t*)&Alo[(r0 + 8) * ASTRA + k0];
        uint32_t al2 = *(const uint32_t*)&Alo[(r0    ) * ASTRA + k0 + 8];
        uint32_t al3 = *(const uint32_t*)&Alo[(r0 + 8) * ASTRA + k0 + 8];
#pragma unroll
        for (int t = 0; t < 8; t++) {
            int fi = s * 512 + (tbase + t) * 32 + lane;
            uint2 bh = WH[fi];
            uint2 bl = __ldg(&g_wfo_lo[fi]);
            MMA16816(c[t], ah0, ah1, ah2, ah3, bh.x, bh.y);
            MMA16816(c[t], ah0, ah1, ah2, ah3, bl.x, bl.y);
            MMA16816(c[t], al0, al1, al2, al3, bh.x, bh.y);
        }
    }

    int mA = m0 + r0;
    int mB = mA + 8;
    int ncol0 = (warp >> 2) * 64 + tig * 2;
#pragma unroll
    for (int t = 0; t < 8; t++) {
        int n0 = ncol0 + t * 8;
        float2 bo = *(const float2*)&b_o[n0];
        if (mA < N_ATOMS) {
            float2 o = make_float2(fmaxf(bo.x + c[t][0], 0.f),
                                   fmaxf(bo.y + c[t][1], 0.f));
            *(float2*)&g_atomh[(size_t)mA * H + n0] = o;
        }
        if (mB < N_ATOMS) {
            float2 o = make_float2(fmaxf(bo.x + c[t][2], 0.f),
                                   fmaxf(bo.y + c[t][3], 0.f));
            *(float2*)&g_atomh[(size_t)mB * H + n0] = o;
        }
    }
}

// ---------------------------------------------------------------
__device__ __forceinline__ int lowerb(const int* __restrict__ a, int n, int key) {
    int lo = 0, hi = n;
    while (lo < hi) {
        int mid = (lo + hi) >> 1;
        if (a[mid] < key) lo = mid + 1; else hi = mid;
    }
    return lo;
}

__global__ void pool_kernel(const int* __restrict__ mol_ids,
                            float* __restrict__ out) {
    int mol = blockIdx.x;
    int tid = threadIdx.x;
    int lo = lowerb(mol_ids, N_ATOMS, mol);
    int hi = lowerb(mol_ids, N_ATOMS, mol + 1);
    float s = 0.f;
    for (int a = lo; a < hi; a++)
        s += g_atomh[(size_t)a * H + tid];
    int cnt = hi - lo;
    out[(size_t)mol * H + tid] = cnt ? s / (float)cnt : 0.f;
}

// ---------------------------------------------------------------
extern "C" void kernel_launch(void* const* d_in, const int* in_sizes, int n_in,
                              void* d_out, int out_size) {
    const float *fatoms = nullptr, *fbonds = nullptr, *tree = nullptr;
    const float *W_i = nullptr, *W_h = nullptr, *W_o = nullptr, *b_o = nullptr;
    const int *agraph = nullptr, *bgraph = nullptr, *mol_ids = nullptr;
    for (int i = 0; i < n_in; i++) {
        switch (in_sizes[i]) {
            case 3500000: fatoms  = (const float*)d_in[i]; break;   // 100000*35
            case 8800000: fbonds  = (const float*)d_in[i]; break;   // 220000*40
            case 2560000: tree    = (const float*)d_in[i]; break;   // 20000*128
            case 1000000: agraph  = (const int*)d_in[i];   break;   // 100000*10
            case 2200000: bgraph  = (const int*)d_in[i];   break;   // 220000*10
            case 100000:  mol_ids = (const int*)d_in[i];   break;
            case 5120:    W_i     = (const float*)d_in[i]; break;   // 40*128
            case 16384:   W_h     = (const float*)d_in[i]; break;   // 128*128
            case 20864:   W_o     = (const float*)d_in[i]; break;   // 163*128
            case 128:     b_o     = (const float*)d_in[i]; break;
        }
    }

    const int BIN_SMEM  = (TM * BF + BF * H) * 4;
    const int BOND_SMEM = BMT * ASTR * 2 * 2 + 4096 * 8 * 2;  // 34816+65536=100352
    const int ATOM_SMEM = 64 * ASTRA * 2 * 2 + NS_A * 512 * 8; // 47104+45056=92160
    cudaFuncSetAttribute(bond_mma_kernel,
                         cudaFuncAttributeMaxDynamicSharedMemorySize, BOND_SMEM);
    cudaFuncSetAttribute(atom_mma_kernel,
                         cudaFuncAttributeMaxDynamicSharedMemorySize, ATOM_SMEM);

    float *msgA, *msgB;
    cudaGetSymbolAddress((void**)&msgA, g_msgA);
    cudaGetSymbolAddress((void**)&msgB, g_msgB);

    int tc_blocks = (N_MESS * H / 4 + 255) / 256;
    tree_copy_kernel<<<tc_blocks, 256>>>(tree);
    prep_w_kernel<<<(8 * 16 * 32 + 255) / 256, 256>>>(W_h);
    prep_wo_kernel<<<(NS_A * 16 * 32 + 255) / 256, 256>>>(W_o);

    int grid_bin = (N_BONDS + TM - 1) / TM;
    binput_kernel<<<grid_bin, TB, BIN_SMEM>>>(fbonds, W_i);

    float* src = msgA;
    float* dst = msgB;
    int grid_mma = (N_BONDS + BMT - 1) / BMT;   // 3438
    for (int it = 0; it < 5; it++) {            // DEPTH-1
        bond_mma_kernel<<<grid_mma, 256, BOND_SMEM>>>(
            src, dst + (size_t)N_MESS * H, bgraph);
        float* t = src; src = dst; dst = t;
    }

    int grid_a = (N_ATOMS + 63) / 64;           // 1563
    atom_mma_kernel<<<grid_a, 256, ATOM_SMEM>>>(src, agraph, fatoms, b_o);

    pool_kernel<<<N_MOLS, H>>>(mol_ids, (float*)d_out);
}